// round 3
// baseline (speedup 1.0000x reference)
#include <cuda_runtime.h>

// Problem constants (fixed shapes from reference):
//   B=4, S=64, F=64, V=16384, E=512, rows = B*S*F = 16384
#define V_DIM 16384
#define E_DIM 512
#define NROWS 16384
#define NF4   (V_DIM / 4)      // 4096 float4 per row
#define NCHUNK 128             // 128 chunks of 32 float4 (128 elements) each

// Warp-per-row early-exit scan with prefetch depth 2, no block barriers.
// Phase A: warp scans its one-hot row in 128-elem chunks; __ballot_sync check;
//          loads for chunks c+1, c+2 already in flight when checking chunk c.
// Phase B: out[row,:] = W[:,idx] + pos_emb[s,:] + fmap_emb[f,:]
//          W gathered column-wise (amplification absorbed by L2; x uses __ldcs
//          evict-first and out uses __stcs so W stays L2-resident).
__global__ void __launch_bounds__(256) combined_embedding_kernel(
    const float* __restrict__ x,
    const float* __restrict__ W,
    const float* __restrict__ pos_emb,
    const float* __restrict__ fmap_emb,
    float* __restrict__ out)
{
    const int warp = threadIdx.x >> 5;
    const int lane = threadIdx.x & 31;
    const int row  = blockIdx.x * 8 + warp;   // 2048 blocks x 8 warps

    const float4* xr = reinterpret_cast<const float4*>(x + (size_t)row * V_DIM);

    // ---- Phase A: pipelined warp scan ----
    float4 c0 = __ldcs(&xr[lane]);            // chunk 0
    float4 c1 = __ldcs(&xr[32 + lane]);       // chunk 1

    int idx = 0;
    #pragma unroll 1
    for (int c = 0; c < NCHUNK; c++) {
        float4 c2;
        if (c + 2 < NCHUNK) c2 = __ldcs(&xr[(c + 2) * 32 + lane]);

        int f = -1;
        const int base = (c * 32 + lane) * 4;
        if (c0.x != 0.0f) f = base + 0;
        if (c0.y != 0.0f) f = base + 1;
        if (c0.z != 0.0f) f = base + 2;
        if (c0.w != 0.0f) f = base + 3;

        unsigned m = __ballot_sync(0xffffffffu, f >= 0);
        if (m) {
            int src = __ffs(m) - 1;
            idx = __shfl_sync(0xffffffffu, f, src);
            break;
        }
        c0 = c1;
        c1 = c2;
    }

    // ---- Phase B: gather + add, warp-wide ----
    const int s = (row >> 6) & 63;   // row = ((b*64)+s)*64 + f
    const int fm = row & 63;

    const float4* pe = reinterpret_cast<const float4*>(pos_emb  + (size_t)s  * E_DIM);
    const float4* fe = reinterpret_cast<const float4*>(fmap_emb + (size_t)fm * E_DIM);
    float4* o = reinterpret_cast<float4*>(out + (size_t)row * E_DIM);

    // E=512 -> 128 float4; 32 lanes x 4 each. W gather: column idx, stride V.
    #pragma unroll
    for (int j = 0; j < 4; j++) {
        const int q  = j * 32 + lane;   // float4 index within the row
        const int e  = q * 4;           // first embedding dim of this float4
        float4 p = __ldg(&pe[q]);
        float4 g = __ldg(&fe[q]);
        float4 r;
        r.x = __ldg(&W[(size_t)(e + 0) * V_DIM + idx]) + p.x + g.x;
        r.y = __ldg(&W[(size_t)(e + 1) * V_DIM + idx]) + p.y + g.y;
        r.z = __ldg(&W[(size_t)(e + 2) * V_DIM + idx]) + p.z + g.z;
        r.w = __ldg(&W[(size_t)(e + 3) * V_DIM + idx]) + p.w + g.w;
        __stcs(&o[q], r);               // streaming store: don't evict W from L2
    }
}

extern "C" void kernel_launch(void* const* d_in, const int* in_sizes, int n_in,
                              void* d_out, int out_size) {
    const float* x        = (const float*)d_in[0];  // [4,64,64,16384]
    const float* W        = (const float*)d_in[1];  // [512,16384]
    const float* pos_emb  = (const float*)d_in[2];  // [256,512]
    const float* fmap_emb = (const float*)d_in[3];  // [256,512]
    float* out = (float*)d_out;                     // [4,64,64,512]

    (void)in_sizes; (void)n_in; (void)out_size;

    combined_embedding_kernel<<<NROWS / 8, 256>>>(x, W, pos_emb, fmap_emb, out);
}